// round 7
// baseline (speedup 1.0000x reference)
#include <cuda_runtime.h>
#include <cuda_bf16.h>
#include <cstddef>
#include <cstdint>

// Problem constants (fixed by the dataset)
#define BATCH 64
#define LSEQ  512
#define DIN   256
#define HDIM  256
#define H3    768
#define ADIM  128
#define DEPTH 4
#define NROWS (LSEQ * BATCH)   // 32768
#define NCAT  896              // 768 xp + 128 xa

#define CLUSTER_NCTAS 8
#define ROWS_PER_CTA  112
#define NBAT          4
#define NCLU          16
#define SCAN_THREADS  896
#define HPBUF         3584     // floats per parity buffer: 896 rows x 4 batches
#define HPBYTES       14336

// SMEM weight layout: row r = 72 float4 (8 kq-blocks of 9: 8 data + 1 pad)
#define WROW_F4  72
// hT layout: float4 per k (4 batches), 33-f4 blocks (32 data + 1 pad)
#define HT_F4(k)        ((((k) >> 5) * 33) + ((k) & 31))
#define HT_FLT(k, b)    ((((k) >> 5) * 132) + (((k) & 31) * 4) + (b))

// ---------------- scratch (device globals; no allocation allowed) -------------
__device__ float g_hseq[(size_t)NROWS * HDIM];
__device__ float g_xpa [(size_t)NROWS * NCAT];
__device__ float g_Wcat[(size_t)DIN * NCAT];
__device__ float g_Ut2 [(size_t)(H3 + ADIM) * HDIM];
__device__ unsigned char g_mask[BATCH * LSEQ];

// ---------------------------------- helpers ----------------------------------
__device__ __forceinline__ float warp_sum(float v) {
#pragma unroll
    for (int o = 16; o > 0; o >>= 1) v += __shfl_down_sync(0xffffffffu, v, o);
    return v;
}
__device__ __forceinline__ float sigmoidf(float x) { return 1.0f / (1.0f + expf(-x)); }

__device__ __forceinline__ void fma2(unsigned long long& d, unsigned long long a,
                                     unsigned long long b) {
    asm("fma.rn.f32x2 %0, %1, %2, %0;" : "+l"(d) : "l"(a), "l"(b));
}
__device__ __forceinline__ unsigned long long pk(float lo, float hi) {
    unsigned long long r;
    asm("mov.b64 %0, {%1, %2};" : "=l"(r) : "f"(lo), "f"(hi));
    return r;
}
__device__ __forceinline__ float2 upk(unsigned long long v) {
    float2 r;
    asm("mov.b64 {%0, %1}, %2;" : "=f"(r.x), "=f"(r.y) : "l"(v));
    return r;
}
__device__ __forceinline__ uint32_t smem_u32(const void* p) {
    uint32_t a;
    asm("{ .reg .u64 t; cvta.to.shared.u64 t, %1; cvt.u32.u64 %0, t; }" : "=r"(a) : "l"(p));
    return a;
}
// consumer wait: acquire at CLUSTER scope (peers' DSMEM stores must be visible)
__device__ __forceinline__ void mbar_wait_cluster(uint32_t addr, uint32_t parity) {
    uint32_t done;
    asm volatile(
        "{\n\t.reg .pred p;\n\t"
        "mbarrier.try_wait.parity.acquire.cluster.shared::cta.b64 p, [%1], %2;\n\t"
        "selp.b32 %0, 1, 0, p;\n\t}"
        : "=r"(done) : "r"(addr), "r"(parity) : "memory");
    while (!done) {
        asm volatile(
            "{\n\t.reg .pred p;\n\t"
            "mbarrier.try_wait.parity.acquire.cluster.shared::cta.b64 p, [%1], %2, 0x989680;\n\t"
            "selp.b32 %0, 1, 0, p;\n\t}"
            : "=r"(done) : "r"(addr), "r"(parity) : "memory");
    }
}

// ----------------- fused prep: Ut2 transpose + Wcat + mask --------------------
__global__ void prep_fused(const float* __restrict__ U, const float* __restrict__ Ua1,
                           const float* __restrict__ W, const float* __restrict__ Wa1,
                           const unsigned char* __restrict__ m8) {
    int k = blockIdx.x;
    if (k < H3 + ADIM) {
        int i = threadIdx.x;
        float v = (k < H3) ? U[(size_t)i * H3 + k] : Ua1[(size_t)i * ADIM + (k - H3)];
        g_Ut2[(size_t)k * HDIM + i] = v;
    } else if (k < H3 + ADIM + DIN) {
        int r = k - (H3 + ADIM);
        for (int n = threadIdx.x; n < NCAT; n += blockDim.x)
            g_Wcat[(size_t)r * NCAT + n] =
                (n < H3) ? W[(size_t)r * H3 + n] : Wa1[(size_t)r * ADIM + (n - H3)];
    } else {
        __shared__ int mode;
        if (threadIdx.x == 0) {
            int nz = 0;
            for (int i = 0; i < 64; i++) nz |= m8[4 * i + 1] | m8[4 * i + 2] | m8[4 * i + 3];
            mode = nz ? 1 : 0;
        }
        __syncthreads();
        if (mode) {
            for (int i = threadIdx.x; i < BATCH * LSEQ; i += blockDim.x)
                g_mask[i] = m8[i] ? 1 : 0;
        } else {
            const int* m32 = (const int*)m8;
            for (int i = threadIdx.x; i < BATCH * LSEQ; i += blockDim.x)
                g_mask[i] = m32[i] ? 1 : 0;
        }
    }
}

// ------------------------------- tiled SGEMM (f32x2) --------------------------
template <bool REMAP>
__global__ void __launch_bounds__(256) sgemm_kernel(
    const float* __restrict__ A, const float* __restrict__ Bm,
    const float* __restrict__ bias, float* __restrict__ C, int N) {
    const int K = 256;
    __shared__ __align__(16) float Ast[16][68];
    __shared__ __align__(16) float Bs[16][64];
    int t  = threadIdx.x;
    int m0 = blockIdx.y * 64;
    int n0 = blockIdx.x * 64;
    int ty = t >> 4, tx = t & 15;

    unsigned long long acc2[4][2];
#pragma unroll
    for (int i = 0; i < 4; i++) { acc2[i][0] = 0ull; acc2[i][1] = 0ull; }

    int ar = t >> 2;
    int ak = (t & 3) * 4;
    int arow = m0 + ar;
    const float* Aptr;
    if (REMAP) {
        int b = arow & 63, l = arow >> 6;
        Aptr = A + ((size_t)b * LSEQ + l) * K;
    } else {
        Aptr = A + (size_t)arow * K;
    }
    int bk = t >> 4;
    int bn = (t & 15) * 4;

    for (int k0 = 0; k0 < K; k0 += 16) {
        float4 av = *(const float4*)(Aptr + k0 + ak);
        Ast[ak + 0][ar] = av.x;
        Ast[ak + 1][ar] = av.y;
        Ast[ak + 2][ar] = av.z;
        Ast[ak + 3][ar] = av.w;
        *(float4*)(&Bs[bk][bn]) = *(const float4*)(Bm + (size_t)(k0 + bk) * N + n0 + bn);
        __syncthreads();
#pragma unroll
        for (int kk = 0; kk < 16; kk++) {
            float4 a  = *(const float4*)(&Ast[kk][ty * 4]);
            float4 bb = *(const float4*)(&Bs[kk][tx * 4]);
            unsigned long long b01 = pk(bb.x, bb.y), b23 = pk(bb.z, bb.w);
            unsigned long long ax = pk(a.x, a.x), ay = pk(a.y, a.y);
            unsigned long long az = pk(a.z, a.z), aw = pk(a.w, a.w);
            fma2(acc2[0][0], ax, b01); fma2(acc2[0][1], ax, b23);
            fma2(acc2[1][0], ay, b01); fma2(acc2[1][1], ay, b23);
            fma2(acc2[2][0], az, b01); fma2(acc2[2][1], az, b23);
            fma2(acc2[3][0], aw, b01); fma2(acc2[3][1], aw, b23);
        }
        __syncthreads();
    }
#pragma unroll
    for (int i = 0; i < 4; i++) {
        int row = m0 + ty * 4 + i;
        float2 v01 = upk(acc2[i][0]), v23 = upk(acc2[i][1]);
        float4 v;
        v.x = v01.x; v.y = v01.y; v.z = v23.x; v.w = v23.y;
        if (bias) {
            v.x += bias[n0 + tx * 4 + 0];
            v.y += bias[n0 + tx * 4 + 1];
            v.z += bias[n0 + tx * 4 + 2];
            v.w += bias[n0 + tx * 4 + 3];
        }
        *(float4*)(&C[(size_t)row * N + n0 + tx * 4]) = v;
    }
}

// ---------------- cluster scan: DSMEM push + mbarrier (no cluster barrier) ----
// Rank p computes rows [112p,112p+112) x 4 batches and PUSHES the float4 results
// into all 8 CTAs' s_hp via st.shared::cluster; one elected thread per CTA does
// fence.acq_rel.cluster + 8 remote mbarrier arrives. Consumers wait with
// acquire.cluster parity try_wait. Phase B is fully local & symmetric.
__global__ void __cluster_dims__(CLUSTER_NCTAS, 1, 1) __launch_bounds__(SCAN_THREADS, 1)
scan4_kernel(int d,
             const float* __restrict__ bg,
             const float* __restrict__ gammas,
             const float* __restrict__ betas,
             const float* __restrict__ ba1,
             const float* __restrict__ Wa2,
             const float* __restrict__ ba2,
             float* __restrict__ out, int out_size) {
    extern __shared__ __align__(16) float sm[];
    // sm[0..3]: two mbarriers (2 x u64)
    float* Wsm   = sm + 4;                            // 32256
    float* s_hT  = Wsm  + ROWS_PER_CTA * WROW_F4 * 4; // 1056
    float* s_hp  = s_hT + 1056;                       // 2*3584
    float* s_xpa = s_hp + 2 * HPBUF;                  // 2*4*896 = 7168
    float* c_g0  = s_xpa + 2 * NBAT * NCAT;           // 768
    float* c_b0  = c_g0 + H3;
    float* c_g1  = c_b0 + H3;
    float* c_b1  = c_g1 + H3;
    float* c_bg  = c_b1 + H3;
    float* c_ba1 = c_bg + H3;                         // 128
    float* c_wa2 = c_ba1 + ADIM;                      // 256
    float* s_rhp = c_wa2 + 2 * ADIM;                  // 8 (u32 remote hp bases)
    float* s_red = s_rhp + 8;                         // 64
    float* s_stat= s_red + 64;                        // 8
    float* s_xscr= s_stat + 8;                        // 24
    float* s_xst = s_xscr + 24;                       // 16
    unsigned char* s_mask = (unsigned char*)(s_xst + 16); // 4*512 bytes

    const int t    = threadIdx.x;
    const int rank = blockIdx.x & (CLUSTER_NCTAS - 1);
    const int clu  = blockIdx.x >> 3;
    const int b0   = clu * NBAT;
    const int wid  = t >> 5;

    const uint32_t mb   = smem_u32(sm);          // mbar[0] at mb, mbar[1] at mb+8
    const uint32_t hpb  = smem_u32(s_hp);

    // ---- init: mbarriers + remote hp bases ----
    if (t == 0) {
        asm volatile("mbarrier.init.shared.b64 [%0], %1;" :: "r"(mb),     "r"(8u) : "memory");
        asm volatile("mbarrier.init.shared.b64 [%0], %1;" :: "r"(mb + 8), "r"(8u) : "memory");
    }
    if (t < 8) {
        uint32_t ra;
        asm("mapa.shared::cluster.u32 %0, %1, %2;" : "=r"(ra) : "r"(hpb), "r"(t));
        ((uint32_t*)s_rhp)[t] = ra;
    }

    // ---- weight slice into padded smem layout ----
    {
        const float4* src = (const float4*)(g_Ut2 + (size_t)(ROWS_PER_CTA * rank) * HDIM);
        float4* dst = (float4*)Wsm;
        for (int i = t; i < ROWS_PER_CTA * 64; i += SCAN_THREADS) {
            int row = i >> 6, c4 = i & 63;
            dst[row * WROW_F4 + (c4 >> 3) * 9 + (c4 & 7)] = src[(size_t)row * 64 + c4];
        }
    }
    for (int i = t; i < H3; i += SCAN_THREADS) {
        c_g0[i] = gammas[i];
        c_b0[i] = betas[i];
        c_g1[i] = gammas[H3 + i];
        c_b1[i] = betas[H3 + i];
        c_bg[i] = bg[i];
    }
    if (t < ADIM)     c_ba1[t] = ba1[t];
    if (t < 2 * ADIM) c_wa2[t] = Wa2[t];
    for (int i = t; i < NBAT * LSEQ; i += SCAN_THREADS)
        s_mask[i] = g_mask[(b0 + (i >> 9)) * LSEQ + (i & 511)];
    for (int i = t; i < 1056; i += SCAN_THREADS) s_hT[i] = 0.0f;

    // xpa(0) for all 4 batches into buffer 0 (one float4 per thread)
    const int pf_bb = t / 224, pf_c4 = t - 224 * (t / 224);
    ((float4*)s_xpa)[pf_bb * 224 + pf_c4] =
        *((const float4*)g_xpa + ((size_t)(b0 + pf_bb)) * 224 + pf_c4);
    __syncthreads();

    // mbarriers visible cluster-wide before any remote arrive/store
    asm volatile("barrier.cluster.arrive.aligned;" ::: "memory");
    asm volatile("barrier.cluster.wait.aligned;" ::: "memory");

    // prologue: xp-LN stats for step 0 (buffer 0), 4 batches by helper warps
    if (t >= 512) {
        int u = t - 512, bb = u / 96, q = u - 96 * bb;
        const float* xr = s_xpa + bb * NCAT;
        float s = 0.f, qq = 0.f;
#pragma unroll
        for (int j = 0; j < 8; j++) { float v = xr[q + 96 * j]; s += v; qq += v * v; }
        s = warp_sum(s); qq = warp_sum(qq);
        if ((u & 31) == 0) { int w = u >> 5; s_xscr[w * 2] = s; s_xscr[w * 2 + 1] = qq; }
    }
    __syncthreads();
    if (t >= 8 && t < 12) {
        int bb = t - 8;
        float S = 0.f, Q = 0.f;
#pragma unroll
        for (int j = 0; j < 3; j++) { S += s_xscr[(bb * 3 + j) * 2]; Q += s_xscr[(bb * 3 + j) * 2 + 1]; }
        float mu = S * (1.0f / 768.0f), var = Q * (1.0f / 768.0f) - mu * mu;
        s_xst[bb] = mu; s_xst[4 + bb] = rsqrtf(var + 1e-5f);
    }
    __syncthreads();

    const bool write_full = (out_size >= 409600);
    const int r_ = t >> 3, kq = t & 7;
    const float4* wf = (const float4*)Wsm + r_ * WROW_F4 + kq * 9;
    const float4* ht = (const float4*)s_hT;
    const float ba2_0 = ba2[0], ba2_1 = ba2[1];

    for (int l = 0; l < LSEQ; ++l) {
        const int par = l & 1, nxt = par ^ 1;
        const int lp = (l + 1 < LSEQ) ? l + 1 : l;

        // prefetch xpa(l+1) — all threads, latency hidden under matvec
        float4 pf = *((const float4*)g_xpa +
                      ((size_t)lp * BATCH + b0 + pf_bb) * 224 + pf_c4);

        // ---- phase A: matvec (weights once, 4 batches via f32x2) ----
        {
            unsigned long long a01 = 0ull, a23 = 0ull;
#pragma unroll
            for (int i = 0; i < 8; i++) {
                float4 w  = wf[i];
                float4 h0 = ht[kq * 33 + i * 4 + 0];
                float4 h1 = ht[kq * 33 + i * 4 + 1];
                float4 h2 = ht[kq * 33 + i * 4 + 2];
                float4 h3 = ht[kq * 33 + i * 4 + 3];
                fma2(a01, pk(w.x, w.x), pk(h0.x, h0.y)); fma2(a23, pk(w.x, w.x), pk(h0.z, h0.w));
                fma2(a01, pk(w.y, w.y), pk(h1.x, h1.y)); fma2(a23, pk(w.y, w.y), pk(h1.z, h1.w));
                fma2(a01, pk(w.z, w.z), pk(h2.x, h2.y)); fma2(a23, pk(w.z, w.z), pk(h2.z, h2.w));
                fma2(a01, pk(w.w, w.w), pk(h3.x, h3.y)); fma2(a23, pk(w.w, w.w), pk(h3.z, h3.w));
            }
            float2 v01 = upk(a01), v23 = upk(a23);
            float d0 = v01.x, d1 = v01.y, d2 = v23.x, d3 = v23.y;
#pragma unroll
            for (int m = 1; m < 8; m <<= 1) {
                d0 += __shfl_xor_sync(0xffffffffu, d0, m);
                d1 += __shfl_xor_sync(0xffffffffu, d1, m);
                d2 += __shfl_xor_sync(0xffffffffu, d2, m);
                d3 += __shfl_xor_sync(0xffffffffu, d3, m);
            }
            if (kq == 0) {
                // push this row's float4 into every CTA's s_hp (incl. self)
                uint32_t off = (uint32_t)par * HPBYTES +
                               (uint32_t)(rank * ROWS_PER_CTA + r_) * 16u;
#pragma unroll
                for (int rr = 0; rr < 8; rr++) {
                    uint32_t ad = ((const uint32_t*)s_rhp)[rr] + off;
                    asm volatile("st.shared::cluster.v4.f32 [%0], {%1, %2, %3, %4};"
                                 :: "r"(ad), "f"(d0), "f"(d1), "f"(d2), "f"(d3) : "memory");
                }
            }
        }
        __syncthreads();   // all remote stores issued & CTA-ordered

        if (t == 0) {
            asm volatile("fence.acq_rel.cluster;" ::: "memory");
            uint32_t lb = mb + (uint32_t)par * 8u;
#pragma unroll
            for (int rr = 0; rr < 8; rr++) {
                asm volatile(
                    "{\n\t.reg .b32 ra;\n\t"
                    "mapa.shared::cluster.u32 ra, %0, %1;\n\t"
                    "mbarrier.arrive.release.cluster.shared::cluster.b64 _, [ra];\n\t}"
                    :: "r"(lb), "r"(rr) : "memory");
            }
        }
        mbar_wait_cluster(mb + (uint32_t)par * 8u, (uint32_t)((l >> 1) & 1));

        // ---- phase B (all local): LN stats | pf store ----
        const float* hp = s_hp + par * HPBUF;
        if (t < 512) {
            int bb = t >> 7, q = t & 127;
            float s = 0.f, qq = 0.f;
#pragma unroll
            for (int j = 0; j < 6; j++) {
                float v = hp[(q + 128 * j) * 4 + bb];
                s += v; qq += v * v;
            }
            s = warp_sum(s); qq = warp_sum(qq);
            if ((t & 31) == 0) { s_red[wid] = s; s_red[16 + wid] = qq; }
        }
        ((float4*)(s_xpa + nxt * (NBAT * NCAT)))[pf_bb * 224 + pf_c4] = pf;
        __syncthreads();

        if (t < 4) {
            float S = s_red[4 * t] + s_red[4 * t + 1] + s_red[4 * t + 2] + s_red[4 * t + 3];
            float Q = s_red[16 + 4 * t] + s_red[17 + 4 * t] + s_red[18 + 4 * t] + s_red[19 + 4 * t];
            float mu  = S * (1.0f / 768.0f);
            float var = Q * (1.0f / 768.0f) - mu * mu;
            s_stat[t]     = mu;
            s_stat[4 + t] = rsqrtf(var + 1e-5f);
        } else if (t >= 512) {
            int u = t - 512, bb = u / 96, q = u - 96 * bb;
            const float* xn = s_xpa + (nxt * NBAT + bb) * NCAT;
            float s = 0.f, qq = 0.f;
#pragma unroll
            for (int j = 0; j < 8; j++) { float v = xn[q + 96 * j]; s += v; qq += v * v; }
            s = warp_sum(s); qq = warp_sum(qq);
            if ((u & 31) == 0) { int w = u >> 5; s_xscr[w * 2] = s; s_xscr[w * 2 + 1] = qq; }
        }
        __syncthreads();

        // ---- gates + action (t<512) | xst finalize (helpers) ----
        if (t < 512) {
            int col = t & 255;
#pragma unroll
            for (int rep = 0; rep < 2; rep++) {
                int bb = (t >> 8) + rep * 2;
                float mu = s_stat[bb], rs = s_stat[4 + bb];
                float mux = s_xst[par * 8 + bb], rsx = s_xst[par * 8 + 4 + bb];
                const float* xr = s_xpa + (par * NBAT + bb) * NCAT;
                float x0 = c_g0[col]       * (xr[col]       - mux) * rsx + c_b0[col];
                float x1 = c_g0[col + 256] * (xr[col + 256] - mux) * rsx + c_b0[col + 256];
                float x2 = c_g0[col + 512] * (xr[col + 512] - mux) * rsx + c_b0[col + 512];
                float hp0 = (hp[col * 4 + bb]         - mu) * rs * c_g1[col]       + c_b1[col];
                float hp1 = (hp[(col + 256) * 4 + bb] - mu) * rs * c_g1[col + 256] + c_b1[col + 256];
                float hp2 = (hp[(col + 512) * 4 + bb] - mu) * rs * c_g1[col + 512] + c_b1[col + 512];
                float r  = sigmoidf(x0 + hp0     + c_bg[col]);
                float z  = sigmoidf(x1 + hp1     + c_bg[col + 256]);
                float hh = tanhf   (x2 + r * hp2 + c_bg[col + 512]);
                float hold = s_hT[HT_FLT(col, bb)];
                float hn = z * hold + (1.0f - z) * hh;
                float ho = s_mask[bb * LSEQ + l] ? hn : hold;
                s_hT[HT_FLT(col, bb)] = ho;
                if (rank == bb) {
                    g_hseq[((size_t)l * BATCH + b0 + bb) * HDIM + col] = ho;
                    if (d == DEPTH - 1 && l == LSEQ - 1 && out_size >= BATCH * HDIM)
                        out[(b0 + bb) * HDIM + col] = ho;
                }
            }
            // action head
            int bb = t >> 7, k = t & 127;
            float a = tanhf(s_xpa[(par * NBAT + bb) * NCAT + H3 + k] +
                            hp[(H3 + k) * 4 + bb] + c_ba1[k]);
            float p0 = warp_sum(a * c_wa2[2 * k]);
            float p1 = warp_sum(a * c_wa2[2 * k + 1]);
            if ((t & 31) == 0) { s_red[32 + wid] = p0; s_red[48 + wid] = p1; }
        } else if (t >= 512 && t < 516) {
            int bb = t - 512;
            float S = 0.f, Q = 0.f;
#pragma unroll
            for (int j = 0; j < 3; j++) { S += s_xscr[(bb * 3 + j) * 2]; Q += s_xscr[(bb * 3 + j) * 2 + 1]; }
            float mu = S * (1.0f / 768.0f), var = Q * (1.0f / 768.0f) - mu * mu;
            s_xst[nxt * 8 + bb] = mu; s_xst[nxt * 8 + 4 + bb] = rsqrtf(var + 1e-5f);
        }
        __syncthreads();

        if (t < 4) {
            float l0 = s_red[32 + 4 * t] + s_red[33 + 4 * t] + s_red[34 + 4 * t] + s_red[35 + 4 * t] + ba2_0;
            float l1 = s_red[48 + 4 * t] + s_red[49 + 4 * t] + s_red[50 + 4 * t] + s_red[51 + 4 * t] + ba2_1;
            unsigned char mt  = s_mask[t * LSEQ + l];
            unsigned char act = ((l1 > l0) && mt) ? 1 : 0;
            s_mask[t * LSEQ + l] = act;                    // next-depth mask (local)
            if (rank == 4 + t) {
                g_mask[(b0 + t) * LSEQ + l] = act;
                if (write_full) {
                    float m = fmaxf(l0, l1);
                    float e0 = expf(l0 - m), e1 = expf(l1 - m);
                    float inv = 1.0f / (e0 + e1);
                    size_t ai = (size_t)BATCH * HDIM + ((size_t)((b0 + t) * DEPTH + d)) * LSEQ + l;
                    out[ai] = act ? 1.0f : 0.0f;
                    size_t pi = (size_t)BATCH * HDIM + (size_t)BATCH * DEPTH * LSEQ +
                                (((size_t)((b0 + t) * DEPTH + d)) * LSEQ + l) * 2;
                    out[pi]     = e0 * inv;
                    out[pi + 1] = e1 * inv;
                }
            }
        }
        __syncthreads();   // s_hT / s_mask / s_red / s_xst ready for next step
    }

    // no CTA may exit while peers might still store into its SMEM
    asm volatile("barrier.cluster.arrive.aligned;" ::: "memory");
    asm volatile("barrier.cluster.wait.aligned;" ::: "memory");
}

// --------------------------------- launcher ----------------------------------
extern "C" void kernel_launch(void* const* d_in, const int* in_sizes, int n_in,
                              void* d_out, int out_size) {
    const float* x     = (const float*)d_in[0];
    const unsigned char* mask = (const unsigned char*)d_in[1];
    const float* W_emb = (const float*)d_in[2];
    const float* b_emb = (const float*)d_in[3];
    const float* W     = (const float*)d_in[4];
    const float* U     = (const float*)d_in[5];
    const float* bgate = (const float*)d_in[6];
    const float* Wa1   = (const float*)d_in[7];
    const float* Ua1   = (const float*)d_in[8];
    const float* ba1   = (const float*)d_in[9];
    const float* Wa2   = (const float*)d_in[10];
    const float* ba2   = (const float*)d_in[11];
    const float* gammas = (const float*)d_in[12];
    const float* betas  = (const float*)d_in[13];
    float* out = (float*)d_out;

    float *hseq, *xpa, *wcat;
    cudaGetSymbolAddress((void**)&hseq, g_hseq);
    cudaGetSymbolAddress((void**)&xpa, g_xpa);
    cudaGetSymbolAddress((void**)&wcat, g_Wcat);

    const int scan_smem =
        (4 + ROWS_PER_CTA * WROW_F4 * 4 + 1056 + 2 * HPBUF + 2 * NBAT * NCAT +
         5 * H3 + ADIM + 2 * ADIM + 8 + 64 + 8 + 24 + 16) * 4 + NBAT * LSEQ;
    static int attr_done = 0;
    if (!attr_done) {
        cudaFuncSetAttribute(scan4_kernel, cudaFuncAttributeMaxDynamicSharedMemorySize, scan_smem);
        attr_done = 1;
    }

    prep_fused<<<H3 + ADIM + DIN + 1, HDIM>>>(U, Ua1, W, Wa1, mask);
    sgemm_kernel<true><<<dim3(HDIM / 64, NROWS / 64), 256>>>(x, W_emb, b_emb, hseq, HDIM);

    for (int d = 0; d < DEPTH; d++) {
        sgemm_kernel<false><<<dim3(NCAT / 64, NROWS / 64), 256>>>(hseq, wcat, nullptr, xpa, NCAT);
        scan4_kernel<<<NCLU * CLUSTER_NCTAS, SCAN_THREADS, scan_smem>>>(
            d, bgate, gammas, betas, ba1, Wa2, ba2, out, out_size);
    }
}

// round 8
// speedup vs baseline: 2.9367x; 2.9367x over previous
#include <cuda_runtime.h>
#include <cuda_bf16.h>
#include <cstddef>
#include <cstdint>

// Problem constants (fixed by the dataset)
#define BATCH 64
#define LSEQ  512
#define DIN   256
#define HDIM  256
#define H3    768
#define ADIM  128
#define DEPTH 4
#define NROWS (LSEQ * BATCH)   // 32768

#define CLUSTER_NCTAS 8
#define ROWS_PER_CTA  96       // 768 / 8
#define NBAT          4
#define NCLU          16
#define SCAN_THREADS  896
#define GOUT_F4       100      // 96 data float4 + 8 stats floats + pad
#define CLUBUF        (CLUSTER_NCTAS * GOUT_F4 * 4)   // 3200 floats per parity
#define SL_STRIDE     520      // steplist ints per batch (513 used)

// SMEM weight layout: row r = 72 float4 (8 kq-blocks of 9: 8 data + 1 pad)
#define WROW_F4  72
// hT layout: float4 per k (4 batches), 33-f4 blocks (32 data + 1 pad)
#define HT_F4(k)        ((((k) >> 5) * 33) + ((k) & 31))
#define HT_FLT(k, b)    ((((k) >> 5) * 132) + (((k) & 31) * 4) + (b))

// ---------------- scratch (device globals; no allocation allowed) -------------
__device__ float g_hseq[(size_t)NROWS * HDIM];
__device__ float g_xp  [(size_t)NROWS * H3];
__device__ float g_xa  [(size_t)NROWS * ADIM];
__device__ float g_Ut  [(size_t)H3 * HDIM];       // U^T (768x256)
__device__ float g_hp  [(size_t)NCLU * 2 * CLUBUF];
__device__ int   g_steplist[BATCH * SL_STRIDE];
__device__ int   g_src  [BATCH * LSEQ];
__device__ int   g_nsteps[BATCH];
__device__ unsigned char g_mask[BATCH * LSEQ];

// ---------------------------------- helpers ----------------------------------
__device__ __forceinline__ float warp_sum(float v) {
#pragma unroll
    for (int o = 16; o > 0; o >>= 1) v += __shfl_down_sync(0xffffffffu, v, o);
    return v;
}
__device__ __forceinline__ float sigmoidf(float x) { return 1.0f / (1.0f + expf(-x)); }

__device__ __forceinline__ void fma2(unsigned long long& d, unsigned long long a,
                                     unsigned long long b) {
    asm("fma.rn.f32x2 %0, %1, %2, %0;" : "+l"(d) : "l"(a), "l"(b));
}
__device__ __forceinline__ unsigned long long pk(float lo, float hi) {
    unsigned long long r;
    asm("mov.b64 %0, {%1, %2};" : "=l"(r) : "f"(lo), "f"(hi));
    return r;
}
__device__ __forceinline__ float2 upk(unsigned long long v) {
    float2 r;
    asm("mov.b64 {%0, %1}, %2;" : "=f"(r.x), "=f"(r.y) : "l"(v));
    return r;
}

// ----------------- prep: U transpose + mask copy ------------------------------
__global__ void prep_fused(const float* __restrict__ U,
                           const unsigned char* __restrict__ m8) {
    int k = blockIdx.x;
    if (k < H3) {
        int i = threadIdx.x;  // 0..255
        g_Ut[(size_t)k * HDIM + i] = U[(size_t)i * H3 + k];
    } else {
        __shared__ int mode;
        if (threadIdx.x == 0) {
            int nz = 0;
            for (int i = 0; i < 64; i++) nz |= m8[4 * i + 1] | m8[4 * i + 2] | m8[4 * i + 3];
            mode = nz ? 1 : 0;
        }
        __syncthreads();
        if (mode) {
            for (int i = threadIdx.x; i < BATCH * LSEQ; i += blockDim.x)
                g_mask[i] = m8[i] ? 1 : 0;
        } else {
            const int* m32 = (const int*)m8;
            for (int i = threadIdx.x; i < BATCH * LSEQ; i += blockDim.x)
                g_mask[i] = m32[i] ? 1 : 0;
        }
    }
}

// ---------------- steplist: per-batch unmasked-step list + fill sources -------
__global__ void steplist_kernel() {
    int b = blockIdx.x, t = threadIdx.x;   // 64 blocks x 32 threads
    __shared__ unsigned char m[LSEQ];
    __shared__ int sn;
    for (int i = t; i < LSEQ; i += 32) m[i] = g_mask[b * LSEQ + i];
    __syncwarp();
    if (t == 0) {
        int n = 0, src = -1;
        for (int l = 0; l < LSEQ; l++) {
            if (m[l]) { g_steplist[b * SL_STRIDE + n] = l; n++; src = l; }
            else      { g_src[b * LSEQ + l] = src; }
        }
        g_nsteps[b] = n;
        sn = n;
    }
    __syncwarp();
    for (int i = sn + t; i <= LSEQ; i += 32) g_steplist[b * SL_STRIDE + i] = -1;
}

// ------------------------------- tiled SGEMM (f32x2) --------------------------
// MODE 0: plain. MODE 1: A row r -> x[b=r&63][l=r>>6] (embed). MODE 2: A row
// r -> hseq row r-64 (zeros for r<64), and C += result (shift-accumulate).
template <int MODE>
__global__ void __launch_bounds__(256) sgemm_kernel(
    const float* __restrict__ A, const float* __restrict__ Bm,
    const float* __restrict__ bias, float* __restrict__ C, int N) {
    const int K = 256;
    __shared__ __align__(16) float Ast[16][68];
    __shared__ __align__(16) float Bs[16][64];
    int t  = threadIdx.x;
    int m0 = blockIdx.y * 64;
    int n0 = blockIdx.x * 64;
    int ty = t >> 4, tx = t & 15;

    unsigned long long acc2[4][2];
#pragma unroll
    for (int i = 0; i < 4; i++) { acc2[i][0] = 0ull; acc2[i][1] = 0ull; }

    int ar = t >> 2;
    int ak = (t & 3) * 4;
    int arow = m0 + ar;
    const float* Aptr;
    if (MODE == 1) {
        int b = arow & 63, l = arow >> 6;
        Aptr = A + ((size_t)b * LSEQ + l) * K;
    } else if (MODE == 2) {
        Aptr = A + (size_t)(arow - 64) * K;
    } else {
        Aptr = A + (size_t)arow * K;
    }
    const bool avalid = (MODE != 2) || (arow >= 64);
    int bk = t >> 4;
    int bn = (t & 15) * 4;

    for (int k0 = 0; k0 < K; k0 += 16) {
        float4 av = make_float4(0.f, 0.f, 0.f, 0.f);
        if (avalid) av = *(const float4*)(Aptr + k0 + ak);
        Ast[ak + 0][ar] = av.x;
        Ast[ak + 1][ar] = av.y;
        Ast[ak + 2][ar] = av.z;
        Ast[ak + 3][ar] = av.w;
        *(float4*)(&Bs[bk][bn]) = *(const float4*)(Bm + (size_t)(k0 + bk) * N + n0 + bn);
        __syncthreads();
#pragma unroll
        for (int kk = 0; kk < 16; kk++) {
            float4 a  = *(const float4*)(&Ast[kk][ty * 4]);
            float4 bb = *(const float4*)(&Bs[kk][tx * 4]);
            unsigned long long b01 = pk(bb.x, bb.y), b23 = pk(bb.z, bb.w);
            unsigned long long ax = pk(a.x, a.x), ay = pk(a.y, a.y);
            unsigned long long az = pk(a.z, a.z), aw = pk(a.w, a.w);
            fma2(acc2[0][0], ax, b01); fma2(acc2[0][1], ax, b23);
            fma2(acc2[1][0], ay, b01); fma2(acc2[1][1], ay, b23);
            fma2(acc2[2][0], az, b01); fma2(acc2[2][1], az, b23);
            fma2(acc2[3][0], aw, b01); fma2(acc2[3][1], aw, b23);
        }
        __syncthreads();
    }
#pragma unroll
    for (int i = 0; i < 4; i++) {
        int row = m0 + ty * 4 + i;
        float2 v01 = upk(acc2[i][0]), v23 = upk(acc2[i][1]);
        float4 v;
        v.x = v01.x; v.y = v01.y; v.z = v23.x; v.w = v23.y;
        if (MODE != 2 && bias) {
            v.x += bias[n0 + tx * 4 + 0];
            v.y += bias[n0 + tx * 4 + 1];
            v.z += bias[n0 + tx * 4 + 2];
            v.w += bias[n0 + tx * 4 + 3];
        }
        float4* cp = (float4*)(&C[(size_t)row * N + n0 + tx * 4]);
        if (MODE == 2) {
            float4 o = *cp;
            v.x += o.x; v.y += o.y; v.z += o.z; v.w += o.w;
        }
        *cp = v;
    }
}

// -------------------- fill: masked hseq rows = carried h ----------------------
__global__ void fill_kernel(float* __restrict__ hseq) {
    int l = blockIdx.x, b = blockIdx.y, t = threadIdx.x;   // 64 threads
    if (g_mask[b * LSEQ + l]) return;
    int src = g_src[b * LSEQ + l];
    float4 v = make_float4(0.f, 0.f, 0.f, 0.f);
    if (src >= 0) v = ((const float4*)hseq)[((size_t)src * BATCH + b) * 64 + t];
    ((float4*)hseq)[((size_t)l * BATCH + b) * 64 + t] = v;
}

// -------------------- head: bulk action/policy + next mask --------------------
__global__ void head_kernel(int d, const float* __restrict__ lin,
                            const float* __restrict__ ba1,
                            const float* __restrict__ Wa2,
                            const float* __restrict__ ba2,
                            const float* __restrict__ hseq,
                            float* __restrict__ out, int out_size) {
    int r = blockIdx.x;            // (l,b) row: r = l*64 + b
    int l = r >> 6, b = r & 63;
    int t = threadIdx.x;           // 128
    __shared__ float s[8];

    float v = tanhf(lin[(size_t)r * ADIM + t] + ba1[t]);
    float p0 = warp_sum(v * Wa2[2 * t]);
    float p1 = warp_sum(v * Wa2[2 * t + 1]);
    if ((t & 31) == 0) { s[(t >> 5) * 2] = p0; s[(t >> 5) * 2 + 1] = p1; }

    // final hidden state: depth 3, last step (hseq already filled)
    if (d == DEPTH - 1 && l == LSEQ - 1 && out_size >= BATCH * HDIM) {
        const float* hr = hseq + ((size_t)(LSEQ - 1) * BATCH + b) * HDIM;
        out[b * HDIM + t]       = hr[t];
        out[b * HDIM + 128 + t] = hr[128 + t];
    }
    __syncthreads();
    if (t == 0) {
        float l0 = s[0] + s[2] + s[4] + s[6] + ba2[0];
        float l1 = s[1] + s[3] + s[5] + s[7] + ba2[1];
        unsigned char mt = g_mask[b * LSEQ + l];
        unsigned char act = ((l1 > l0) && mt) ? 1 : 0;
        g_mask[b * LSEQ + l] = act;      // next-depth mask
        if (out_size >= 409600) {
            float m = fmaxf(l0, l1);
            float e0 = expf(l0 - m), e1 = expf(l1 - m);
            float inv = 1.0f / (e0 + e1);
            size_t ai = (size_t)BATCH * HDIM + ((size_t)(b * DEPTH + d)) * LSEQ + l;
            out[ai] = act ? 1.0f : 0.0f;
            size_t pi = (size_t)BATCH * HDIM + (size_t)BATCH * DEPTH * LSEQ +
                        (((size_t)(b * DEPTH + d)) * LSEQ + l) * 2;
            out[pi]     = e0 * inv;
            out[pi + 1] = e1 * inv;
        }
    }
}

// --------------- cluster scan: recurrence only, skip masked steps -------------
// 16 clusters x 8 CTAs; cluster owns 4 batches. Each batch advances through ITS
// OWN unmasked-step list in lockstep by list index. Matvec = 768 rows (U only);
// action head removed (bulk pass). R5 exchange protocol (parity gout + single
// cluster barrier + __ldcv gather).
__global__ void __cluster_dims__(CLUSTER_NCTAS, 1, 1) __launch_bounds__(SCAN_THREADS, 1)
scan5_kernel(const float* __restrict__ bg,
             const float* __restrict__ gammas,
             const float* __restrict__ betas) {
    extern __shared__ __align__(16) float sm[];
    float* Wsm   = sm;                              // 96*288 = 27648
    float* s_hT  = Wsm  + ROWS_PER_CTA * WROW_F4 * 4; // 1056
    float* s_hp  = s_hT + 1056;                     // 768*5 = 3840
    float* s_xpa = s_hp + 768 * 5;                  // 2*4*768 = 6144
    float* c_g0  = s_xpa + 2 * NBAT * H3;           // 768
    float* c_b0  = c_g0 + H3;
    float* c_g1  = c_b0 + H3;
    float* c_b1  = c_g1 + H3;
    float* c_bg  = c_b1 + H3;
    float* s_lnA = c_bg + H3;                       // 24*8 = 192
    float* s_red = s_lnA + 192;                     // 64
    float* s_stat= s_red + 64;                      // 8
    float* s_xst = s_stat + 8;                      // 16 (2 par x (mu[4],rs[4]))
    int*   s_lb  = (int*)(s_xst + 16);              // 8 (2 par x 4 batches)

    const int t    = threadIdx.x;
    const int rank = blockIdx.x & (CLUSTER_NCTAS - 1);
    const int clu  = blockIdx.x >> 3;
    const int b0   = clu * NBAT;
    const int lane = t & 31, wid = t >> 5;

    // ---- weight slice (rows 96*rank..+95 of U^T) into padded layout ----
    {
        const float4* src = (const float4*)(g_Ut + (size_t)(ROWS_PER_CTA * rank) * HDIM);
        float4* dst = (float4*)Wsm;
        for (int i = t; i < ROWS_PER_CTA * 64; i += SCAN_THREADS) {
            int row = i >> 6, c4 = i & 63;
            dst[row * WROW_F4 + (c4 >> 3) * 9 + (c4 & 7)] = src[(size_t)row * 64 + c4];
        }
    }
    for (int i = t; i < H3; i += SCAN_THREADS) {
        c_g0[i] = gammas[i];
        c_b0[i] = betas[i];
        c_g1[i] = gammas[H3 + i];
        c_b1[i] = betas[H3 + i];
        c_bg[i] = bg[i];
    }
    for (int i = t; i < 1056; i += SCAN_THREADS) s_hT[i] = 0.0f;

    // maxit = max unmasked count over the cluster's 4 batches (uniform/thread)
    int maxit = 0;
#pragma unroll
    for (int i = 0; i < 4; i++) {
        int n = g_nsteps[b0 + i];
        maxit = (n > maxit) ? n : maxit;
    }
    if (t < 4) s_lb[t] = g_steplist[(b0 + t) * SL_STRIDE];
    __syncthreads();

    // prologue: load xpa for it=0 (active batches only)
    if (t < 768) {
        int bb = t / 192, c4 = t - 192 * bb;
        int lb = s_lb[bb];
        if (lb >= 0)
            ((float4*)s_xpa)[bb * 192 + c4] =
                *((const float4*)g_xp + ((size_t)lb * BATCH + b0 + bb) * 192 + c4);
    }
    __syncthreads();
    // xp-LN stats for it=0 (helpers: 4 warps, one per batch)
    if (t >= 768) {
        int u = t - 768, bb = u >> 5;
        const float* xr = s_xpa + bb * H3;
        float s = 0.f, q = 0.f;
#pragma unroll
        for (int j = 0; j < 24; j++) { float v = xr[(u & 31) + 32 * j]; s += v; q += v * v; }
        s = warp_sum(s); q = warp_sum(q);
        if ((u & 31) == 0) {
            float mu = s * (1.0f / 768.0f), var = q * (1.0f / 768.0f) - mu * mu;
            s_xst[bb] = mu; s_xst[4 + bb] = rsqrtf(var + 1e-5f);
        }
    }
    __syncthreads();

    const int r_ = t >> 3, kq = t & 7;
    const float4* wf = (const float4*)Wsm + r_ * WROW_F4 + kq * 9;
    const float4* ht = (const float4*)s_hT;
    float* gbase = g_hp + (size_t)clu * (2 * CLUBUF);

    for (int it = 0; it < maxit; ++it) {
        const int par = it & 1, nxt = par ^ 1;
        float* gout = gbase + par * CLUBUF;

        // ---- phase A ----
        float4 pf0, pf1, pf2, pf3, pf4, pf5;
        int pv0 = 0, pv1 = 0, pv2 = 0, pv3 = 0, pv4 = 0, pv5 = 0;
        if (t < 768) {
            // matvec: weights once, 4 batches via f32x2
            unsigned long long a01 = 0ull, a23 = 0ull;
#pragma unroll
            for (int i = 0; i < 8; i++) {
                float4 w  = wf[i];
                float4 h0 = ht[kq * 33 + i * 4 + 0];
                float4 h1 = ht[kq * 33 + i * 4 + 1];
                float4 h2 = ht[kq * 33 + i * 4 + 2];
                float4 h3 = ht[kq * 33 + i * 4 + 3];
                fma2(a01, pk(w.x, w.x), pk(h0.x, h0.y)); fma2(a23, pk(w.x, w.x), pk(h0.z, h0.w));
                fma2(a01, pk(w.y, w.y), pk(h1.x, h1.y)); fma2(a23, pk(w.y, w.y), pk(h1.z, h1.w));
                fma2(a01, pk(w.z, w.z), pk(h2.x, h2.y)); fma2(a23, pk(w.z, w.z), pk(h2.z, h2.w));
                fma2(a01, pk(w.w, w.w), pk(h3.x, h3.y)); fma2(a23, pk(w.w, w.w), pk(h3.z, h3.w));
            }
            float2 v01 = upk(a01), v23 = upk(a23);
            float d0 = v01.x, d1 = v01.y, d2 = v23.x, d3 = v23.y;
#pragma unroll
            for (int m = 1; m < 8; m <<= 1) {
                d0 += __shfl_xor_sync(0xffffffffu, d0, m);
                d1 += __shfl_xor_sync(0xffffffffu, d1, m);
                d2 += __shfl_xor_sync(0xffffffffu, d2, m);
                d3 += __shfl_xor_sync(0xffffffffu, d3, m);
            }
            if (kq == 0) {
                float4 o; o.x = d0; o.y = d1; o.z = d2; o.w = d3;
                ((float4*)gout)[rank * GOUT_F4 + r_] = o;
            }
            // LN partials (sum & sumsq over the warp's 4 rows, all rows valid)
            float q0 = d0 * d0, q1 = d1 * d1, q2 = d2 * d2, q3 = d3 * d3;
#pragma unroll
            for (int m = 8; m <= 16; m <<= 1) {
                d0 += __shfl_xor_sync(0xffffffffu, d0, m);
                d1 += __shfl_xor_sync(0xffffffffu, d1, m);
                d2 += __shfl_xor_sync(0xffffffffu, d2, m);
                d3 += __shfl_xor_sync(0xffffffffu, d3, m);
                q0 += __shfl_xor_sync(0xffffffffu, q0, m);
                q1 += __shfl_xor_sync(0xffffffffu, q1, m);
                q2 += __shfl_xor_sync(0xffffffffu, q2, m);
                q3 += __shfl_xor_sync(0xffffffffu, q3, m);
            }
            if (lane == 0) {
                s_lnA[wid * 8 + 0] = d0; s_lnA[wid * 8 + 1] = d1;
                s_lnA[wid * 8 + 2] = d2; s_lnA[wid * 8 + 3] = d3;
                s_lnA[wid * 8 + 4] = q0; s_lnA[wid * 8 + 5] = q1;
                s_lnA[wid * 8 + 6] = q2; s_lnA[wid * 8 + 7] = q3;
            }
        } else {
            // helpers: read next step indices + prefetch xp rows for it+1
            int u = t - 768;
            int lbv[4];
#pragma unroll
            for (int i = 0; i < 4; i++)
                lbv[i] = g_steplist[(b0 + i) * SL_STRIDE + it + 1];
            if (u < 4) s_lb[nxt * 4 + u] = lbv[u];
            const float4* xpf4 = (const float4*)g_xp;
#pragma unroll
            for (int j = 0; j < 6; j++) {
                int idx = u + 128 * j;        // 0..767
                int bb = idx / 192, c4 = idx - 192 * bb;
                int lb = lbv[bb];
                float4 vv = make_float4(0.f, 0.f, 0.f, 0.f);
                int valid = (lb >= 0);
                if (valid) vv = xpf4[((size_t)lb * BATCH + b0 + bb) * 192 + c4];
                switch (j) {
                    case 0: pf0 = vv; pv0 = valid; break;
                    case 1: pf1 = vv; pv1 = valid; break;
                    case 2: pf2 = vv; pv2 = valid; break;
                    case 3: pf3 = vv; pv3 = valid; break;
                    case 4: pf4 = vv; pv4 = valid; break;
                    case 5: pf5 = vv; pv5 = valid; break;
                }
            }
        }
        __syncthreads();
        if (t < 8) {
            float acc = 0.f;
#pragma unroll
            for (int w = 0; w < 24; w++) acc += s_lnA[w * 8 + t];
            gout[rank * GOUT_F4 * 4 + 384 + t] = acc;
        }

        asm volatile("barrier.cluster.arrive.aligned;" ::: "memory");
        asm volatile("barrier.cluster.wait.aligned;" ::: "memory");

        // ---- phase B: gather hp + stats; helpers store prefetch ----
        if (t < 768) {
            int rank_r = t / 96, wrow_r = t - 96 * rank_r;
            float4 v = __ldcv((const float4*)gout + rank_r * GOUT_F4 + wrow_r);
            float* dst = s_hp + t * 5;
            dst[0] = v.x; dst[1] = v.y; dst[2] = v.z; dst[3] = v.w;
        }
        if (t < 64) {
            int r8 = t >> 3, s8 = t & 7;
            s_red[t] = __ldcv(gout + r8 * GOUT_F4 * 4 + 384 + s8);
        }
        if (t >= 768) {
            int u = t - 768;
            float* xd = s_xpa + nxt * (NBAT * H3);
#pragma unroll
            for (int j = 0; j < 6; j++) {
                int idx = u + 128 * j;
                int valid = (j == 0) ? pv0 : (j == 1) ? pv1 : (j == 2) ? pv2 :
                            (j == 3) ? pv3 : (j == 4) ? pv4 : pv5;
                float4 vv = (j == 0) ? pf0 : (j == 1) ? pf1 : (j == 2) ? pf2 :
                            (j == 3) ? pf3 : (j == 4) ? pf4 : pf5;
                if (valid) ((float4*)xd)[idx] = vv;
            }
        }
        __syncthreads();

        // hp LN mu/rstd per batch | xp stats for it+1 (helpers)
        if (t < 4) {
            float S = 0.f, Q = 0.f;
#pragma unroll
            for (int r8 = 0; r8 < 8; r8++) { S += s_red[r8 * 8 + t]; Q += s_red[r8 * 8 + 4 + t]; }
            float mu  = S * (1.0f / 768.0f);
            float var = Q * (1.0f / 768.0f) - mu * mu;
            s_stat[t]     = mu;
            s_stat[4 + t] = rsqrtf(var + 1e-5f);
        } else if (t >= 768) {
            int u = t - 768, bb = u >> 5;
            const float* xr = s_xpa + nxt * (NBAT * H3) + bb * H3;
            float s = 0.f, q = 0.f;
#pragma unroll
            for (int j = 0; j < 24; j++) { float v = xr[(u & 31) + 32 * j]; s += v; q += v * v; }
            s = warp_sum(s); q = warp_sum(q);
            if ((u & 31) == 0) {
                float mu = s * (1.0f / 768.0f), var = q * (1.0f / 768.0f) - mu * mu;
                s_xst[nxt * 8 + bb] = mu; s_xst[nxt * 8 + 4 + bb] = rsqrtf(var + 1e-5f);
            }
        }
        __syncthreads();

        // ---- gates (t<512, 2 batches each), only for active batches ----
        if (t < 512) {
            int col = t & 255;
#pragma unroll
            for (int rep = 0; rep < 2; rep++) {
                int bb = (t >> 8) + rep * 2;
                int lb = s_lb[par * 4 + bb];
                if (lb >= 0) {
                    float mu = s_stat[bb], rs = s_stat[4 + bb];
                    float mux = s_xst[par * 8 + bb], rsx = s_xst[par * 8 + 4 + bb];
                    const float* xr = s_xpa + (par * NBAT + bb) * H3;
                    float x0 = c_g0[col]       * (xr[col]       - mux) * rsx + c_b0[col];
                    float x1 = c_g0[col + 256] * (xr[col + 256] - mux) * rsx + c_b0[col + 256];
                    float x2 = c_g0[col + 512] * (xr[col + 512] - mux) * rsx + c_b0[col + 512];
                    float hp0 = (s_hp[col * 5 + bb]         - mu) * rs * c_g1[col]       + c_b1[col];
                    float hp1 = (s_hp[(col + 256) * 5 + bb] - mu) * rs * c_g1[col + 256] + c_b1[col + 256];
                    float hp2 = (s_hp[(col + 512) * 5 + bb] - mu) * rs * c_g1[col + 512] + c_b1[col + 512];
                    float r  = sigmoidf(x0 + hp0     + c_bg[col]);
                    float z  = sigmoidf(x1 + hp1     + c_bg[col + 256]);
                    float hh = tanhf   (x2 + r * hp2 + c_bg[col + 512]);
                    float hold = s_hT[HT_FLT(col, bb)];
                    float ho = z * hold + (1.0f - z) * hh;
                    s_hT[HT_FLT(col, bb)] = ho;
                    if (rank == bb)
                        g_hseq[((size_t)lb * BATCH + b0 + bb) * HDIM + col] = ho;
                }
            }
        }
        __syncthreads();   // s_hT / s_lb / s_xpa stable before next iteration
    }
}

// --------------------------------- launcher ----------------------------------
extern "C" void kernel_launch(void* const* d_in, const int* in_sizes, int n_in,
                              void* d_out, int out_size) {
    const float* x     = (const float*)d_in[0];
    const unsigned char* mask = (const unsigned char*)d_in[1];
    const float* W_emb = (const float*)d_in[2];
    const float* b_emb = (const float*)d_in[3];
    const float* W     = (const float*)d_in[4];
    const float* U     = (const float*)d_in[5];
    const float* bgate = (const float*)d_in[6];
    const float* Wa1   = (const float*)d_in[7];
    const float* Ua1   = (const float*)d_in[8];
    const float* ba1   = (const float*)d_in[9];
    const float* Wa2   = (const float*)d_in[10];
    const float* ba2   = (const float*)d_in[11];
    const float* gammas = (const float*)d_in[12];
    const float* betas  = (const float*)d_in[13];
    float* out = (float*)d_out;

    float *hseq, *xp, *xa;
    cudaGetSymbolAddress((void**)&hseq, g_hseq);
    cudaGetSymbolAddress((void**)&xp, g_xp);
    cudaGetSymbolAddress((void**)&xa, g_xa);

    const int scan_smem =
        (ROWS_PER_CTA * WROW_F4 * 4 + 1056 + 768 * 5 + 2 * NBAT * H3 +
         5 * H3 + 192 + 64 + 8 + 16 + 8) * 4;
    static int attr_done = 0;
    if (!attr_done) {
        cudaFuncSetAttribute(scan5_kernel, cudaFuncAttributeMaxDynamicSharedMemorySize, scan_smem);
        attr_done = 1;
    }

    prep_fused<<<H3 + 1, HDIM>>>(U, mask);
    sgemm_kernel<1><<<dim3(HDIM / 64, NROWS / 64), 256>>>(x, W_emb, b_emb, hseq, HDIM);

    for (int d = 0; d < DEPTH; d++) {
        steplist_kernel<<<BATCH, 32>>>();
        sgemm_kernel<0><<<dim3(H3 / 64, NROWS / 64), 256>>>(hseq, W, nullptr, xp, H3);
        sgemm_kernel<0><<<dim3(ADIM / 64, NROWS / 64), 256>>>(hseq, Wa1, nullptr, xa, ADIM);
        scan5_kernel<<<NCLU * CLUSTER_NCTAS, SCAN_THREADS, scan_smem>>>(bgate, gammas, betas);
        fill_kernel<<<dim3(LSEQ, BATCH), 64>>>(hseq);
        sgemm_kernel<2><<<dim3(ADIM / 64, NROWS / 64), 256>>>(hseq, Ua1, nullptr, xa, ADIM);
        head_kernel<<<NROWS, 128>>>(d, xa, ba1, Wa2, ba2, hseq, out, out_size);
    }
}

// round 9
// speedup vs baseline: 3.1012x; 1.0560x over previous
#include <cuda_runtime.h>
#include <cuda_bf16.h>
#include <cstddef>
#include <cstdint>

// Problem constants (fixed by the dataset)
#define BATCH 64
#define LSEQ  512
#define DIN   256
#define HDIM  256
#define H3    768
#define ADIM  128
#define DEPTH 4
#define NROWS (LSEQ * BATCH)   // 32768

#define CLUSTER_NCTAS 8
#define ROWS_PER_CTA  96       // 768 / 8
#define NBAT          4
#define NCLU          16
#define SCAN_THREADS  896
#define GOUT_F4       100      // 96 data float4 + 8 stats floats + pad
#define CLUBUF        (CLUSTER_NCTAS * GOUT_F4 * 4)   // 3200 floats per parity
#define SL_STRIDE     520      // steplist ints per batch (513 used)

// SMEM weight layout: row r = 72 float4 (8 kq-blocks of 9: 8 data + 1 pad)
#define WROW_F4  72
// hT layout: float4 per k (4 batches), 33-f4 blocks (32 data + 1 pad)
#define HT_F4(k)        ((((k) >> 5) * 33) + ((k) & 31))
#define HT_FLT(k, b)    ((((k) >> 5) * 132) + (((k) & 31) * 4) + (b))

// ---------------- scratch (device globals; no allocation allowed) -------------
__device__ float g_h0  [(size_t)NROWS * HDIM];
__device__ float g_h1  [(size_t)NROWS * HDIM];
__device__ float g_xp  [(size_t)NROWS * H3];
__device__ float g_xa  [(size_t)NROWS * ADIM];
__device__ float g_Ut  [(size_t)H3 * HDIM];       // U^T (768x256)
__device__ float g_hp  [(size_t)NCLU * 2 * CLUBUF];
__device__ int   g_steplist[BATCH * SL_STRIDE];
__device__ int   g_src  [BATCH * LSEQ];
__device__ int   g_nsteps[BATCH];
__device__ unsigned char g_mask[BATCH * LSEQ];

// ---------------------------------- helpers ----------------------------------
__device__ __forceinline__ float warp_sum(float v) {
#pragma unroll
    for (int o = 16; o > 0; o >>= 1) v += __shfl_down_sync(0xffffffffu, v, o);
    return v;
}
// fast activations (err ~1e-6; saturate correctly at +/-inf)
__device__ __forceinline__ float fsig(float x) {
    float e = __expf(-x);
    return __fdividef(1.0f, 1.0f + e);
}
__device__ __forceinline__ float ftanhf(float x) {
    float e = __expf(2.0f * x);
    return 1.0f - __fdividef(2.0f, e + 1.0f);
}

__device__ __forceinline__ void fma2(unsigned long long& d, unsigned long long a,
                                     unsigned long long b) {
    asm("fma.rn.f32x2 %0, %1, %2, %0;" : "+l"(d) : "l"(a), "l"(b));
}
__device__ __forceinline__ unsigned long long pk(float lo, float hi) {
    unsigned long long r;
    asm("mov.b64 %0, {%1, %2};" : "=l"(r) : "f"(lo), "f"(hi));
    return r;
}
__device__ __forceinline__ float2 upk(unsigned long long v) {
    float2 r;
    asm("mov.b64 {%0, %1}, %2;" : "=f"(r.x), "=f"(r.y) : "l"(v));
    return r;
}
__device__ __forceinline__ float sum4(float4 v) { return (v.x + v.y) + (v.z + v.w); }
__device__ __forceinline__ float sq4(float4 v)  { return (v.x * v.x + v.y * v.y) + (v.z * v.z + v.w * v.w); }

// ----------------- prep: U transpose + mask copy + depth-0 plan ---------------
__global__ void prep_fused(const float* __restrict__ U,
                           const unsigned char* __restrict__ m8) {
    int k = blockIdx.x;
    if (k < H3) {
        int i = threadIdx.x;  // 0..255
        g_Ut[(size_t)k * HDIM + i] = U[(size_t)i * H3 + k];
        return;
    }
    // block H3: mask dtype-detect + copy + per-batch plan
    __shared__ unsigned char smm[BATCH * LSEQ];
    __shared__ int mode;
    int t = threadIdx.x;
    if (t == 0) {
        int nz = 0;
        for (int i = 0; i < 64; i++) nz |= m8[4 * i + 1] | m8[4 * i + 2] | m8[4 * i + 3];
        mode = nz ? 1 : 0;
    }
    __syncthreads();
    if (mode) {
        for (int i = t; i < BATCH * LSEQ; i += blockDim.x) {
            unsigned char v = m8[i] ? 1 : 0;
            g_mask[i] = v; smm[i] = v;
        }
    } else {
        const int* m32 = (const int*)m8;
        for (int i = t; i < BATCH * LSEQ; i += blockDim.x) {
            unsigned char v = m32[i] ? 1 : 0;
            g_mask[i] = v; smm[i] = v;
        }
    }
    __syncthreads();
    if (t < BATCH) {
        int b = t, n = 0, src = -1;
        for (int l = 0; l < LSEQ; l++) {
            if (smm[b * LSEQ + l]) { g_steplist[b * SL_STRIDE + n] = l; n++; src = l; }
            else                   { g_src[b * LSEQ + l] = src; }
        }
        g_nsteps[b] = n;
        for (int i = n; i <= LSEQ; i++) g_steplist[b * SL_STRIDE + i] = -1;
    }
}

// ---------------- plan (d>=1): unmasked-step list + fill sources --------------
__global__ void plan_kernel() {
    int b = blockIdx.x, t = threadIdx.x;   // 64 blocks x 32 threads
    __shared__ unsigned char m[LSEQ];
    __shared__ int sn;
    for (int i = t; i < LSEQ; i += 32) m[i] = g_mask[b * LSEQ + i];
    __syncwarp();
    if (t == 0) {
        int n = 0, src = -1;
        for (int l = 0; l < LSEQ; l++) {
            if (m[l]) { g_steplist[b * SL_STRIDE + n] = l; n++; src = l; }
            else      { g_src[b * LSEQ + l] = src; }
        }
        g_nsteps[b] = n;
        sn = n;
    }
    __syncwarp();
    for (int i = sn + t; i <= LSEQ; i += 32) g_steplist[b * SL_STRIDE + i] = -1;
}

// ------------------------------- tiled SGEMM (f32x2) --------------------------
// MODE 0: plain. MODE 1: A row r -> x[b=r&63][l=r>>6] (embed). MODE 2: A row
// r -> A row r-64 (zeros for r<64), and C += result (shift-accumulate).
template <int MODE>
__global__ void __launch_bounds__(256) sgemm_kernel(
    const float* __restrict__ A, const float* __restrict__ Bm,
    const float* __restrict__ bias, float* __restrict__ C, int N) {
    const int K = 256;
    __shared__ __align__(16) float Ast[16][68];
    __shared__ __align__(16) float Bs[16][64];
    int t  = threadIdx.x;
    int m0 = blockIdx.y * 64;
    int n0 = blockIdx.x * 64;
    int ty = t >> 4, tx = t & 15;

    unsigned long long acc2[4][2];
#pragma unroll
    for (int i = 0; i < 4; i++) { acc2[i][0] = 0ull; acc2[i][1] = 0ull; }

    int ar = t >> 2;
    int ak = (t & 3) * 4;
    int arow = m0 + ar;
    const float* Aptr;
    if (MODE == 1) {
        int b = arow & 63, l = arow >> 6;
        Aptr = A + ((size_t)b * LSEQ + l) * K;
    } else if (MODE == 2) {
        Aptr = A + (size_t)(arow - 64) * K;
    } else {
        Aptr = A + (size_t)arow * K;
    }
    const bool avalid = (MODE != 2) || (arow >= 64);
    int bk = t >> 4;
    int bn = (t & 15) * 4;

    for (int k0 = 0; k0 < K; k0 += 16) {
        float4 av = make_float4(0.f, 0.f, 0.f, 0.f);
        if (avalid) av = *(const float4*)(Aptr + k0 + ak);
        Ast[ak + 0][ar] = av.x;
        Ast[ak + 1][ar] = av.y;
        Ast[ak + 2][ar] = av.z;
        Ast[ak + 3][ar] = av.w;
        *(float4*)(&Bs[bk][bn]) = *(const float4*)(Bm + (size_t)(k0 + bk) * N + n0 + bn);
        __syncthreads();
#pragma unroll
        for (int kk = 0; kk < 16; kk++) {
            float4 a  = *(const float4*)(&Ast[kk][ty * 4]);
            float4 bb = *(const float4*)(&Bs[kk][tx * 4]);
            unsigned long long b01 = pk(bb.x, bb.y), b23 = pk(bb.z, bb.w);
            unsigned long long ax = pk(a.x, a.x), ay = pk(a.y, a.y);
            unsigned long long az = pk(a.z, a.z), aw = pk(a.w, a.w);
            fma2(acc2[0][0], ax, b01); fma2(acc2[0][1], ax, b23);
            fma2(acc2[1][0], ay, b01); fma2(acc2[1][1], ay, b23);
            fma2(acc2[2][0], az, b01); fma2(acc2[2][1], az, b23);
            fma2(acc2[3][0], aw, b01); fma2(acc2[3][1], aw, b23);
        }
        __syncthreads();
    }
#pragma unroll
    for (int i = 0; i < 4; i++) {
        int row = m0 + ty * 4 + i;
        float2 v01 = upk(acc2[i][0]), v23 = upk(acc2[i][1]);
        float4 v;
        v.x = v01.x; v.y = v01.y; v.z = v23.x; v.w = v23.y;
        if (MODE != 2 && bias) {
            v.x += bias[n0 + tx * 4 + 0];
            v.y += bias[n0 + tx * 4 + 1];
            v.z += bias[n0 + tx * 4 + 2];
            v.w += bias[n0 + tx * 4 + 3];
        }
        float4* cp = (float4*)(&C[(size_t)row * N + n0 + tx * 4]);
        if (MODE == 2) {
            float4 o = *cp;
            v.x += o.x; v.y += o.y; v.z += o.z; v.w += o.w;
        }
        *cp = v;
    }
}

// -------------------- fill: masked h_out rows = carried h ---------------------
__global__ void fill_kernel(float* __restrict__ hout) {
    int l = blockIdx.x, b = blockIdx.y, t = threadIdx.x;   // 64 threads
    if (g_mask[b * LSEQ + l]) return;
    int src = g_src[b * LSEQ + l];
    float4 v = make_float4(0.f, 0.f, 0.f, 0.f);
    if (src >= 0) v = ((const float4*)hout)[((size_t)src * BATCH + b) * 64 + t];
    ((float4*)hout)[((size_t)l * BATCH + b) * 64 + t] = v;
}

// -------------------- head: bulk action/policy + next mask --------------------
__global__ void head_kernel(int d, const float* __restrict__ lin,
                            const float* __restrict__ ba1,
                            const float* __restrict__ Wa2,
                            const float* __restrict__ ba2,
                            const float* __restrict__ hout,
                            float* __restrict__ out, int out_size) {
    int r = blockIdx.x;            // (l,b) row: r = l*64 + b
    int l = r >> 6, b = r & 63;
    int t = threadIdx.x;           // 128
    __shared__ float s[8];

    float v = tanhf(lin[(size_t)r * ADIM + t] + ba1[t]);
    float p0 = warp_sum(v * Wa2[2 * t]);
    float p1 = warp_sum(v * Wa2[2 * t + 1]);
    if ((t & 31) == 0) { s[(t >> 5) * 2] = p0; s[(t >> 5) * 2 + 1] = p1; }

    if (d == DEPTH - 1 && l == LSEQ - 1 && out_size >= BATCH * HDIM) {
        const float* hr = hout + ((size_t)(LSEQ - 1) * BATCH + b) * HDIM;
        out[b * HDIM + t]       = hr[t];
        out[b * HDIM + 128 + t] = hr[128 + t];
    }
    __syncthreads();
    if (t == 0) {
        float l0 = s[0] + s[2] + s[4] + s[6] + ba2[0];
        float l1 = s[1] + s[3] + s[5] + s[7] + ba2[1];
        unsigned char mt = g_mask[b * LSEQ + l];
        unsigned char act = ((l1 > l0) && mt) ? 1 : 0;
        g_mask[b * LSEQ + l] = act;      // next-depth mask
        if (out_size >= 409600) {
            float m = fmaxf(l0, l1);
            float e0 = expf(l0 - m), e1 = expf(l1 - m);
            float inv = 1.0f / (e0 + e1);
            size_t ai = (size_t)BATCH * HDIM + ((size_t)(b * DEPTH + d)) * LSEQ + l;
            out[ai] = act ? 1.0f : 0.0f;
            size_t pi = (size_t)BATCH * HDIM + (size_t)BATCH * DEPTH * LSEQ +
                        (((size_t)(b * DEPTH + d)) * LSEQ + l) * 2;
            out[pi]     = e0 * inv;
            out[pi + 1] = e1 * inv;
        }
    }
}

// --------------- cluster scan: recurrence only, skip masked steps -------------
// 16 clusters x 8 CTAs; cluster owns 4 batches, each on its own unmasked-step
// list (lockstep by index). Single cluster barrier per iteration; stats folded
// into the gather phase (3 __syncthreads total). Writes h to hout (ping-pong).
__global__ void __cluster_dims__(CLUSTER_NCTAS, 1, 1) __launch_bounds__(SCAN_THREADS, 1)
scan6_kernel(const float* __restrict__ bg,
             const float* __restrict__ gammas,
             const float* __restrict__ betas,
             float* __restrict__ hout) {
    extern __shared__ __align__(16) float sm[];
    float* Wsm   = sm;                                // 96*288 = 27648
    float* s_hT  = Wsm  + ROWS_PER_CTA * WROW_F4 * 4; // 1056
    float* s_hp  = s_hT + 1056;                       // 768*5 = 3840
    float* s_xpa = s_hp + 768 * 5;                    // 2*4*768 = 6144
    float* c_g0  = s_xpa + 2 * NBAT * H3;             // 768
    float* c_b0  = c_g0 + H3;
    float* c_g1  = c_b0 + H3;
    float* c_b1  = c_g1 + H3;
    float* c_bg  = c_b1 + H3;
    float* s_lnA = c_bg + H3;                         // 24*8 = 192
    float* s_stat= s_lnA + 192;                       // 8
    float* s_xscr= s_stat + 8;                        // 32 (4 warps x 8)
    float* s_xst = s_xscr + 32;                       // 16 (2 par x (mu[4],rs[4]))
    int*   s_lb  = (int*)(s_xst + 16);                // 8 (2 par x 4 batches)

    const int t    = threadIdx.x;
    const int rank = blockIdx.x & (CLUSTER_NCTAS - 1);
    const int clu  = blockIdx.x >> 3;
    const int b0   = clu * NBAT;
    const int lane = t & 31, wid = t >> 5;

    // ---- weight slice (rows 96*rank..+95 of U^T) into padded layout ----
    {
        const float4* src = (const float4*)(g_Ut + (size_t)(ROWS_PER_CTA * rank) * HDIM);
        float4* dst = (float4*)Wsm;
        for (int i = t; i < ROWS_PER_CTA * 64; i += SCAN_THREADS) {
            int row = i >> 6, c4 = i & 63;
            dst[row * WROW_F4 + (c4 >> 3) * 9 + (c4 & 7)] = src[(size_t)row * 64 + c4];
        }
    }
    for (int i = t; i < H3; i += SCAN_THREADS) {
        c_g0[i] = gammas[i];
        c_b0[i] = betas[i];
        c_g1[i] = gammas[H3 + i];
        c_b1[i] = betas[H3 + i];
        c_bg[i] = bg[i];
    }
    for (int i = t; i < 1056; i += SCAN_THREADS) s_hT[i] = 0.0f;

    int maxit = 0;
#pragma unroll
    for (int i = 0; i < 4; i++) {
        int n = g_nsteps[b0 + i];
        maxit = (n > maxit) ? n : maxit;
    }
    if (t < 4) s_lb[t] = g_steplist[(b0 + t) * SL_STRIDE];
    __syncthreads();

    // prologue: load xpa for it=0 (active batches only)
    if (t < 768) {
        int bb = t / 192, c4 = t - 192 * bb;
        int lb = s_lb[bb];
        if (lb >= 0)
            ((float4*)s_xpa)[bb * 192 + c4] =
                *((const float4*)g_xp + ((size_t)lb * BATCH + b0 + bb) * 192 + c4);
    }
    __syncthreads();
    if (t >= 768) {   // xp stats for it=0 (4 helper warps, one per batch)
        int u = t - 768, bb = u >> 5;
        const float* xr = s_xpa + bb * H3;
        float s = 0.f, q = 0.f;
#pragma unroll
        for (int j = 0; j < 24; j++) { float v = xr[(u & 31) + 32 * j]; s += v; q += v * v; }
        s = warp_sum(s); q = warp_sum(q);
        if ((u & 31) == 0) {
            float mu = s * (1.0f / 768.0f), var = q * (1.0f / 768.0f) - mu * mu;
            s_xst[bb] = mu; s_xst[4 + bb] = rsqrtf(var + 1e-5f);
        }
    }
    __syncthreads();

    const int r_ = t >> 3, kq = t & 7;
    const float4* wf = (const float4*)Wsm + r_ * WROW_F4 + kq * 9;
    const float4* ht = (const float4*)s_hT;
    float* gbase = g_hp + (size_t)clu * (2 * CLUBUF);

    for (int it = 0; it < maxit; ++it) {
        const int par = it & 1, nxt = par ^ 1;
        float* gout = gbase + par * CLUBUF;

        // ================ phase A ================
        float4 pf0, pf1, pf2, pf3, pf4, pf5;
        if (t < 768) {
            unsigned long long a01 = 0ull, a23 = 0ull;
#pragma unroll
            for (int i = 0; i < 8; i++) {
                float4 w  = wf[i];
                float4 h0 = ht[kq * 33 + i * 4 + 0];
                float4 h1 = ht[kq * 33 + i * 4 + 1];
                float4 h2 = ht[kq * 33 + i * 4 + 2];
                float4 h3 = ht[kq * 33 + i * 4 + 3];
                fma2(a01, pk(w.x, w.x), pk(h0.x, h0.y)); fma2(a23, pk(w.x, w.x), pk(h0.z, h0.w));
                fma2(a01, pk(w.y, w.y), pk(h1.x, h1.y)); fma2(a23, pk(w.y, w.y), pk(h1.z, h1.w));
                fma2(a01, pk(w.z, w.z), pk(h2.x, h2.y)); fma2(a23, pk(w.z, w.z), pk(h2.z, h2.w));
                fma2(a01, pk(w.w, w.w), pk(h3.x, h3.y)); fma2(a23, pk(w.w, w.w), pk(h3.z, h3.w));
            }
            float2 v01 = upk(a01), v23 = upk(a23);
            float d0 = v01.x, d1 = v01.y, d2 = v23.x, d3 = v23.y;
#pragma unroll
            for (int m = 1; m < 8; m <<= 1) {
                d0 += __shfl_xor_sync(0xffffffffu, d0, m);
                d1 += __shfl_xor_sync(0xffffffffu, d1, m);
                d2 += __shfl_xor_sync(0xffffffffu, d2, m);
                d3 += __shfl_xor_sync(0xffffffffu, d3, m);
            }
            if (kq == 0) {
                float4 o; o.x = d0; o.y = d1; o.z = d2; o.w = d3;
                ((float4*)gout)[rank * GOUT_F4 + r_] = o;
            }
            float q0 = d0 * d0, q1 = d1 * d1, q2 = d2 * d2, q3 = d3 * d3;
#pragma unroll
            for (int m = 8; m <= 16; m <<= 1) {
                d0 += __shfl_xor_sync(0xffffffffu, d0, m);
                d1 += __shfl_xor_sync(0xffffffffu, d1, m);
                d2 += __shfl_xor_sync(0xffffffffu, d2, m);
                d3 += __shfl_xor_sync(0xffffffffu, d3, m);
                q0 += __shfl_xor_sync(0xffffffffu, q0, m);
                q1 += __shfl_xor_sync(0xffffffffu, q1, m);
                q2 += __shfl_xor_sync(0xffffffffu, q2, m);
                q3 += __shfl_xor_sync(0xffffffffu, q3, m);
            }
            if (lane == 0) {
                s_lnA[wid * 8 + 0] = d0; s_lnA[wid * 8 + 1] = d1;
                s_lnA[wid * 8 + 2] = d2; s_lnA[wid * 8 + 3] = d3;
                s_lnA[wid * 8 + 4] = q0; s_lnA[wid * 8 + 5] = q1;
                s_lnA[wid * 8 + 6] = q2; s_lnA[wid * 8 + 7] = q3;
            }
        } else {
            // helpers: next step indices + prefetch xp(it+1) into registers
            int u = t - 768;
            int lbv[4];
#pragma unroll
            for (int i = 0; i < 4; i++)
                lbv[i] = g_steplist[(b0 + i) * SL_STRIDE + it + 1];
            if (u < 4) s_lb[nxt * 4 + u] = lbv[u];
            const float4* xpf4 = (const float4*)g_xp;
#pragma unroll
            for (int j = 0; j < 6; j++) {
                int idx = u + 128 * j;
                int bb = idx / 192, c4 = idx - 192 * bb;
                int lb = lbv[bb];
                float4 vv = make_float4(0.f, 0.f, 0.f, 0.f);
                if (lb >= 0) vv = xpf4[((size_t)lb * BATCH + b0 + bb) * 192 + c4];
                switch (j) {
                    case 0: pf0 = vv; break;
                    case 1: pf1 = vv; break;
                    case 2: pf2 = vv; break;
                    case 3: pf3 = vv; break;
                    case 4: pf4 = vv; break;
                    case 5: pf5 = vv; break;
                }
            }
        }
        __syncthreads();
        if (t < 8) {
            float acc = 0.f;
#pragma unroll
            for (int w = 0; w < 24; w++) acc += s_lnA[w * 8 + t];
            gout[rank * GOUT_F4 * 4 + 384 + t] = acc;
        }

        asm volatile("barrier.cluster.arrive.aligned;" ::: "memory");
        asm volatile("barrier.cluster.wait.aligned;" ::: "memory");

        // ============ gather phase: hp gather | LN stats | pf store+stats ======
        if (t < 768) {
            int rank_r = t / 96, wrow_r = t - 96 * rank_r;
            float4 v = __ldcv((const float4*)gout + rank_r * GOUT_F4 + wrow_r);
            float* dst = s_hp + t * 5;
            dst[0] = v.x; dst[1] = v.y; dst[2] = v.z; dst[3] = v.w;
            if (t < 4) {   // hp LN mu/rstd straight from gout stats
                float S = 0.f, Q = 0.f;
#pragma unroll
                for (int r8 = 0; r8 < 8; r8++) {
                    S += __ldcv(gout + r8 * GOUT_F4 * 4 + 384 + t);
                    Q += __ldcv(gout + r8 * GOUT_F4 * 4 + 384 + 4 + t);
                }
                float mu  = S * (1.0f / 768.0f);
                float var = Q * (1.0f / 768.0f) - mu * mu;
                s_stat[t]     = mu;
                s_stat[4 + t] = rsqrtf(var + 1e-5f);
            }
        } else {
            int u = t - 768;
            float* xd = s_xpa + nxt * (NBAT * H3);
            ((float4*)xd)[u + 0]   = pf0;
            ((float4*)xd)[u + 128] = pf1;
            ((float4*)xd)[u + 256] = pf2;
            ((float4*)xd)[u + 384] = pf3;
            ((float4*)xd)[u + 512] = pf4;
            ((float4*)xd)[u + 640] = pf5;
            // xp-LN partials for it+1 from registers (batch map: j0->0,
            // j1->u<64?0:1, j2->1, j3->2, j4->u<64?2:3, j5->3)
            float xs0 = sum4(pf0), xq0 = sq4(pf0);
            float xs1 = sum4(pf2), xq1 = sq4(pf2);
            float xs2 = sum4(pf3), xq2 = sq4(pf3);
            float xs3 = sum4(pf5), xq3 = sq4(pf5);
            float s1v = sum4(pf1), q1v = sq4(pf1);
            float s4v = sum4(pf4), q4v = sq4(pf4);
            if (u < 64) { xs0 += s1v; xq0 += q1v; xs2 += s4v; xq2 += q4v; }
            else        { xs1 += s1v; xq1 += q1v; xs3 += s4v; xq3 += q4v; }
#pragma unroll
            for (int m = 1; m < 32; m <<= 1) {
                xs0 += __shfl_xor_sync(0xffffffffu, xs0, m);
                xs1 += __shfl_xor_sync(0xffffffffu, xs1, m);
                xs2 += __shfl_xor_sync(0xffffffffu, xs2, m);
                xs3 += __shfl_xor_sync(0xffffffffu, xs3, m);
                xq0 += __shfl_xor_sync(0xffffffffu, xq0, m);
                xq1 += __shfl_xor_sync(0xffffffffu, xq1, m);
                xq2 += __shfl_xor_sync(0xffffffffu, xq2, m);
                xq3 += __shfl_xor_sync(0xffffffffu, xq3, m);
            }
            if (lane == 0) {
                int w = wid - 24;
                s_xscr[w * 8 + 0] = xs0; s_xscr[w * 8 + 1] = xs1;
                s_xscr[w * 8 + 2] = xs2; s_xscr[w * 8 + 3] = xs3;
                s_xscr[w * 8 + 4] = xq0; s_xscr[w * 8 + 5] = xq1;
                s_xscr[w * 8 + 6] = xq2; s_xscr[w * 8 + 7] = xq3;
            }
        }
        __syncthreads();

        // ============ gates phase (t<512) | xst combine (4 helpers) ============
        if (t < 512) {
            int col = t & 255;
#pragma unroll
            for (int rep = 0; rep < 2; rep++) {
                int bb = (t >> 8) + rep * 2;
                int lb = s_lb[par * 4 + bb];
                if (lb >= 0) {
                    float mu = s_stat[bb], rs = s_stat[4 + bb];
                    float mux = s_xst[par * 8 + bb], rsx = s_xst[par * 8 + 4 + bb];
                    const float* xr = s_xpa + (par * NBAT + bb) * H3;
                    float x0 = c_g0[col]       * (xr[col]       - mux) * rsx + c_b0[col];
                    float x1 = c_g0[col + 256] * (xr[col + 256] - mux) * rsx + c_b0[col + 256];
                    float x2 = c_g0[col + 512] * (xr[col + 512] - mux) * rsx + c_b0[col + 512];
                    float hp0 = (s_hp[col * 5 + bb]         - mu) * rs * c_g1[col]       + c_b1[col];
                    float hp1 = (s_hp[(col + 256) * 5 + bb] - mu) * rs * c_g1[col + 256] + c_b1[col + 256];
                    float hp2 = (s_hp[(col + 512) * 5 + bb] - mu) * rs * c_g1[col + 512] + c_b1[col + 512];
                    float r  = fsig(x0 + hp0     + c_bg[col]);
                    float z  = fsig(x1 + hp1     + c_bg[col + 256]);
                    float hh = ftanhf(x2 + r * hp2 + c_bg[col + 512]);
                    float hold = s_hT[HT_FLT(col, bb)];
                    float ho = z * hold + (1.0f - z) * hh;
                    s_hT[HT_FLT(col, bb)] = ho;
                    if (rank == bb)
                        hout[((size_t)lb * BATCH + b0 + bb) * HDIM + col] = ho;
                }
            }
        } else if (t >= 768 && t < 772) {
            int bb = t - 768;
            float S = s_xscr[bb] + s_xscr[8 + bb] + s_xscr[16 + bb] + s_xscr[24 + bb];
            float Q = s_xscr[4 + bb] + s_xscr[12 + bb] + s_xscr[20 + bb] + s_xscr[28 + bb];
            float mu = S * (1.0f / 768.0f), var = Q * (1.0f / 768.0f) - mu * mu;
            s_xst[nxt * 8 + bb] = mu; s_xst[nxt * 8 + 4 + bb] = rsqrtf(var + 1e-5f);
        }
        __syncthreads();   // s_hT / s_lb / s_xpa / s_xst stable for next iter
    }
}

// --------------------------------- launcher ----------------------------------
extern "C" void kernel_launch(void* const* d_in, const int* in_sizes, int n_in,
                              void* d_out, int out_size) {
    const float* x     = (const float*)d_in[0];
    const unsigned char* mask = (const unsigned char*)d_in[1];
    const float* W_emb = (const float*)d_in[2];
    const float* b_emb = (const float*)d_in[3];
    const float* W     = (const float*)d_in[4];
    const float* U     = (const float*)d_in[5];
    const float* bgate = (const float*)d_in[6];
    const float* Wa1   = (const float*)d_in[7];
    const float* Ua1   = (const float*)d_in[8];
    const float* ba1   = (const float*)d_in[9];
    const float* Wa2   = (const float*)d_in[10];
    const float* ba2   = (const float*)d_in[11];
    const float* gammas = (const float*)d_in[12];
    const float* betas  = (const float*)d_in[13];
    float* out = (float*)d_out;

    float *h0, *h1, *xp, *xa;
    cudaGetSymbolAddress((void**)&h0, g_h0);
    cudaGetSymbolAddress((void**)&h1, g_h1);
    cudaGetSymbolAddress((void**)&xp, g_xp);
    cudaGetSymbolAddress((void**)&xa, g_xa);

    const int scan_smem =
        (ROWS_PER_CTA * WROW_F4 * 4 + 1056 + 768 * 5 + 2 * NBAT * H3 +
         5 * H3 + 192 + 8 + 32 + 16 + 8) * 4;
    static int attr_done = 0;
    if (!attr_done) {
        cudaFuncSetAttribute(scan6_kernel, cudaFuncAttributeMaxDynamicSharedMemorySize, scan_smem);
        attr_done = 1;
    }

    // launch order: 0 prep, 1 embed, 2 gemmH3, 3 SCAN (profiled), ...
    prep_fused<<<H3 + 1, HDIM>>>(U, mask);
    sgemm_kernel<1><<<dim3(HDIM / 64, NROWS / 64), 256>>>(x, W_emb, b_emb, h0, HDIM);

    for (int d = 0; d < DEPTH; d++) {
        float* hin  = (d & 1) ? h1 : h0;
        float* hout = (d & 1) ? h0 : h1;
        sgemm_kernel<0><<<dim3(H3 / 64, NROWS / 64), 256>>>(hin, W, nullptr, xp, H3);
        scan6_kernel<<<NCLU * CLUSTER_NCTAS, SCAN_THREADS, scan_smem>>>(
            bgate, gammas, betas, hout);
        sgemm_kernel<0><<<dim3(ADIM / 64, NROWS / 64), 256>>>(hin, Wa1, nullptr, xa, ADIM);
        fill_kernel<<<dim3(LSEQ, BATCH), 64>>>(hout);
        sgemm_kernel<2><<<dim3(ADIM / 64, NROWS / 64), 256>>>(hout, Ua1, nullptr, xa, ADIM);
        head_kernel<<<NROWS, 128>>>(d, xa, ba1, Wa2, ba2, hout, out, out_size);
        if (d < DEPTH - 1) plan_kernel<<<BATCH, 32>>>();
    }
}